// round 2
// baseline (speedup 1.0000x reference)
#include <cuda_runtime.h>
#include <math.h>
#include <float.h>

#define NB 128          // blocks (co-resident, < SM count)
#define NT 1024         // threads per block
#define N_ 4096
#define S_ 32
#define D_ 128
#define MAXP 4224       // padded max dim for augmented matrices (multiple of 128)
#define ITS 20
#define EPSK 1e-6f

// ------------- persistent scratch (__device__ globals: allocation-free) -------------
__device__ __align__(16) float g_Xg[(size_t)S_ * N_ * D_];   // permuted features [s][r][d]
__device__ float g_nrm[S_ * N_];                             // squared norms [s][r]
__device__ __align__(16) float g_M [(size_t)MAXP * MAXP];    // cost matrix core [nt x nc]
__device__ __align__(16) float g_K [(size_t)MAXP * MAXP];    // K  (row-major, padded w/ zeros)
__device__ __align__(16) float g_KT[(size_t)MAXP * MAXP];    // K^T (row-major, padded w/ zeros)
__device__ __align__(16) float g_u [MAXP];
__device__ __align__(16) float g_bv[MAXP];
__device__ int    g_perm[N_];
__device__ int    g_nt;
__device__ float  g_p;
__device__ float  g_pmax[NB];
__device__ double g_psum[NB];
__device__ double g_pres[NB];
__device__ unsigned long long g_barCnt;   // monotonic; zero-initialized

// ------------- grid barrier: monotonic 64-bit counter (no reset races) -------------
__device__ __forceinline__ void gbar_sync(unsigned long long base, int k) {
    __syncthreads();
    if (threadIdx.x == 0) {
        __threadfence();
        atomicAdd(&g_barCnt, 1ULL);
        unsigned long long tgt = base + (unsigned long long)k * NB;
        while (*(volatile unsigned long long*)&g_barCnt < tgt) { __nanosleep(64); }
        __threadfence();
    }
    __syncthreads();
}
#define GBAR() do { ++barK; gbar_sync(barBase, barK); } while (0)

// ------------- FFMA-only expf (avoids the MUFU.EX2 throughput wall) -------------
__device__ __forceinline__ float fast_exp(float x) {
    const float L2E = 1.4426950408889634f;
    float y = fmaf(x, L2E, 12582912.0f);           // round-to-nearest-int via magic number
    int   n = __float_as_int(y) - 0x4B400000;
    float r = y - 12582912.0f;
    float f = fmaf(x, L2E, -r);                    // f in [-0.5, 0.5]
    float p =        1.540353040e-4f;              // 2^f poly (Taylor in f*ln2)
    p = fmaf(p, f,   1.333355815e-3f);
    p = fmaf(p, f,   9.618129107e-3f);
    p = fmaf(p, f,   5.550410866e-2f);
    p = fmaf(p, f,   2.402265070e-1f);
    p = fmaf(p, f,   6.931471806e-1f);
    p = fmaf(p, f,   1.0f);
    return p * __int_as_float((n + 127) << 23);
}

__device__ __forceinline__ float warpMaxF(float v) {
    #pragma unroll
    for (int o = 16; o; o >>= 1) v = fmaxf(v, __shfl_down_sync(0xffffffffu, v, o));
    return v;
}
__device__ __forceinline__ float warpSumF(float v) {
    #pragma unroll
    for (int o = 16; o; o >>= 1) v += __shfl_down_sync(0xffffffffu, v, o);
    return v;
}
__device__ __forceinline__ double warpSumD(double v) {
    #pragma unroll
    for (int o = 16; o; o >>= 1) v += __shfl_down_sync(0xffffffffu, v, o);
    return v;
}

__global__ void __launch_bounds__(NT, 1)
sinkhorn_all(const float* __restrict__ X, const int* __restrict__ T, float* __restrict__ out)
{
    __shared__ __align__(16) float sh[8448];   // 33 KB scratch, reused by every phase
    __shared__ float  s_f[32];
    __shared__ double s_d[32];
    __shared__ float  s_delta, s_efflam;

    const int tid  = threadIdx.x;
    const int bid  = blockIdx.x;
    const int lane = tid & 31;
    const int wid  = tid >> 5;
    const int gwarp = bid * 32 + wid;
    const int nwarp = NB * 32;

    // barrier base: counter is a multiple of NB at launch start; late readers see < base+NB
    unsigned long long v0 = *(volatile unsigned long long*)&g_barCnt;
    unsigned long long barBase = v0 - (v0 % (unsigned long long)NB);
    int barK = 0;

    // ---------------- A0: block 0 builds stable treated/control permutation ----------------
    if (bid == 0) {
        int* cnt = (int*)sh;
        int base = tid * 4;
        int tv0 = T[base], tv1 = T[base+1], tv2 = T[base+2], tv3 = T[base+3];
        int c = (tv0 > 0) + (tv1 > 0) + (tv2 > 0) + (tv3 > 0);
        cnt[tid] = c;
        __syncthreads();
        for (int off = 1; off < NT; off <<= 1) {
            int vv  = cnt[tid];
            int add = (tid >= off) ? cnt[tid - off] : 0;
            __syncthreads();
            cnt[tid] = vv + add;
            __syncthreads();
        }
        int total = cnt[NT - 1];
        int excl  = cnt[tid] - c;
        int tpos = excl, cpos = total + base - excl;
        if (tv0 > 0) g_perm[tpos++] = base + 0; else g_perm[cpos++] = base + 0;
        if (tv1 > 0) g_perm[tpos++] = base + 1; else g_perm[cpos++] = base + 1;
        if (tv2 > 0) g_perm[tpos++] = base + 2; else g_perm[cpos++] = base + 2;
        if (tv3 > 0) g_perm[tpos++] = base + 3; else g_perm[cpos++] = base + 3;
        if (tid == NT - 1) { g_nt = total; g_p = (float)total / (float)N_; }
    }
    GBAR();

    const int   nt = g_nt;
    const int   nc = N_ - nt;
    const float p  = g_p;
    const int   R = nt + 1, C = nc + 1;
    const int   RP = (R + 127) & ~127;
    const int   CP = (C + 127) & ~127;
    const float a_in = p / (float)nt, a_last = 1.0f - p;
    const float b_in = (1.0f - p) / (float)nc, b_last = p;

    // ---------------- A1: gather rows (treated first) + squared norms ----------------
    for (int job = gwarp; job < S_ * N_; job += nwarp) {
        int s = job >> 12;
        int r = job & (N_ - 1);
        int src = g_perm[r];
        const float4* sp = (const float4*)(X + ((size_t)src * S_ + s) * D_);
        float4 vv = sp[lane];
        ((float4*)(g_Xg + ((size_t)s * N_ + r) * D_))[lane] = vv;
        float sq = vv.x*vv.x + vv.y*vv.y + vv.z*vv.z + vv.w*vv.w;
        sq = warpSumF(sq);
        if (lane == 0) g_nrm[s * N_ + r] = sq;
    }
    GBAR();

    double total = 0.0;   // block0/thread0 accumulator

    // ================== per-timestep loop ==================
    for (int s = 0; s < S_; s++) {
        const float* Xt  = g_Xg + (size_t)s * N_ * D_;
        const float* nrm = g_nrm + s * N_;

        // ---------- B1: M = nx + ny - 2*Xt*Xc^T (128x128 tiles, 4x4/thread), track max+sum ----------
        {
            float* As = sh;
            float* Bs = sh + 4096;
            const int tilesI = (nt + 127) >> 7;
            const int tilesJ = (nc + 127) >> 7;
            const int nTiles = tilesI * tilesJ;
            const int lrow = tid & 127;
            const int ld4  = tid >> 7;      // 0..7
            const int tx = lane;            // col group
            const int ty = wid;             // row group
            float  lmax = -FLT_MAX;
            double lsum = 0.0;

            for (int tile = bid; tile < nTiles; tile += NB) {
                int ti = tile / tilesJ, tj = tile - ti * tilesJ;
                int i0 = ti << 7, j0 = tj << 7;
                int arow = i0 + lrow; if (arow >= nt) arow = nt - 1;
                int brow = j0 + lrow; if (brow >= nc) brow = nc - 1;
                const float* ap = Xt + (size_t)arow * D_ + ld4 * 4;
                const float* bp = Xt + (size_t)(nt + brow) * D_ + ld4 * 4;

                float acc[4][4] = {};

                for (int d0 = 0; d0 < D_; d0 += 32) {
                    __syncthreads();
                    float4 av  = *(const float4*)(ap + d0);
                    float4 bw  = *(const float4*)(bp + d0);
                    int dd0 = ld4 * 4;
                    As[(dd0+0)*128 + lrow] = av.x;  As[(dd0+1)*128 + lrow] = av.y;
                    As[(dd0+2)*128 + lrow] = av.z;  As[(dd0+3)*128 + lrow] = av.w;
                    Bs[(dd0+0)*128 + lrow] = bw.x;  Bs[(dd0+1)*128 + lrow] = bw.y;
                    Bs[(dd0+2)*128 + lrow] = bw.z;  Bs[(dd0+3)*128 + lrow] = bw.w;
                    __syncthreads();
                    #pragma unroll
                    for (int dd = 0; dd < 32; dd++) {
                        float4 a4 = *(const float4*)&As[dd*128 + ty*4];
                        float4 b4 = *(const float4*)&Bs[dd*128 + tx*4];
                        acc[0][0] = fmaf(a4.x, b4.x, acc[0][0]);
                        acc[0][1] = fmaf(a4.x, b4.y, acc[0][1]);
                        acc[0][2] = fmaf(a4.x, b4.z, acc[0][2]);
                        acc[0][3] = fmaf(a4.x, b4.w, acc[0][3]);
                        acc[1][0] = fmaf(a4.y, b4.x, acc[1][0]);
                        acc[1][1] = fmaf(a4.y, b4.y, acc[1][1]);
                        acc[1][2] = fmaf(a4.y, b4.z, acc[1][2]);
                        acc[1][3] = fmaf(a4.y, b4.w, acc[1][3]);
                        acc[2][0] = fmaf(a4.z, b4.x, acc[2][0]);
                        acc[2][1] = fmaf(a4.z, b4.y, acc[2][1]);
                        acc[2][2] = fmaf(a4.z, b4.z, acc[2][2]);
                        acc[2][3] = fmaf(a4.z, b4.w, acc[2][3]);
                        acc[3][0] = fmaf(a4.w, b4.x, acc[3][0]);
                        acc[3][1] = fmaf(a4.w, b4.y, acc[3][1]);
                        acc[3][2] = fmaf(a4.w, b4.z, acc[3][2]);
                        acc[3][3] = fmaf(a4.w, b4.w, acc[3][3]);
                    }
                }
                float tsum = 0.0f;
                #pragma unroll
                for (int rr = 0; rr < 4; rr++) {
                    int i = i0 + ty * 4 + rr;
                    if (i >= nt) break;
                    float nx = nrm[i];
                    #pragma unroll
                    for (int cc = 0; cc < 4; cc++) {
                        int j = j0 + tx * 4 + cc;
                        if (j >= nc) break;
                        float m = fmaf(-2.0f, acc[rr][cc], nx + nrm[nt + j]);
                        g_M[(size_t)i * CP + j] = m;
                        lmax = fmaxf(lmax, m);
                        tsum += m;
                    }
                }
                lsum += (double)tsum;
            }
            lmax = warpMaxF(lmax);
            lsum = warpSumD(lsum);
            __syncthreads();
            if (lane == 0) { s_f[wid] = lmax; s_d[wid] = lsum; }
            __syncthreads();
            if (wid == 0) {
                float  m2 = s_f[lane];
                double s2 = s_d[lane];
                m2 = warpMaxF(m2);
                s2 = warpSumD(s2);
                if (lane == 0) { g_pmax[bid] = m2; g_psum[bid] = s2; }
            }
        }
        GBAR();

        // ---------- B2: every block reduces the 128 partials (identical fixed order) ----------
        if (tid == 0) {
            float  dmax = -FLT_MAX;
            double dsum = 0.0;
            #pragma unroll 8
            for (int k2 = 0; k2 < NB; k2++) {
                dmax = fmaxf(dmax, __ldcg(&g_pmax[k2]));
                dsum += __ldcg(&g_psum[k2]);
            }
            s_delta  = dmax;
            s_efflam = (float)(((double)nt * (double)nc) / dsum);   // lam=1 / mean
        }
        __syncthreads();
        const float delta  = s_delta;
        const float efflam = s_efflam;

        // ---------- B3: K = exp(-efflam*Mt)+eps, K^T via smem transpose; u init ----------
        {
            const int rowStrips = RP >> 5, colStrips = CP >> 7;
            const int nStr = rowStrips * colStrips;
            const int srow = wid;               // 0..31 (row in strip)
            const int tj = tid >> 3;            // 0..127 (KT row within strip)
            const int io = (tid & 7) * 4;       // i-offset for KT float4 write
            const float kdelta = fast_exp(-efflam * delta) + EPSK;

            for (int str = bid; str < nStr; str += NB) {
                int sr = str / colStrips, sc = str - sr * colStrips;
                int i0 = sr << 5, j0 = sc << 7;
                int i = i0 + srow;
                float kq[4];
                #pragma unroll
                for (int q = 0; q < 4; q++) {
                    int j = j0 + lane * 4 + q;
                    float kv;
                    if (i < nt && j < nc) {
                        float m = __ldcg(&g_M[(size_t)i * CP + j]);
                        kv = fast_exp(-efflam * m) + EPSK;
                    } else if (i == nt && j < nc) kv = kdelta;
                    else if (j == nc && i < nt)   kv = kdelta;
                    else if (i == nt && j == nc)  kv = 1.0f + EPSK;
                    else                          kv = 0.0f;
                    kq[q] = kv;
                    sh[srow * 133 + lane * 4 + q] = kv;
                }
                *(float4*)&g_K[(size_t)i * CP + j0 + lane * 4] =
                    make_float4(kq[0], kq[1], kq[2], kq[3]);
                __syncthreads();
                float4 tv4 = make_float4(sh[(io+0)*133 + tj], sh[(io+1)*133 + tj],
                                         sh[(io+2)*133 + tj], sh[(io+3)*133 + tj]);
                *(float4*)&g_KT[(size_t)(j0 + tj) * RP + i0 + io] = tv4;
                __syncthreads();
            }
            if (bid == 0) {
                for (int r2 = tid; r2 < RP; r2 += NT) {
                    float av = (r2 < nt) ? a_in : ((r2 == nt) ? a_last : 0.0f);
                    g_u[r2] = av;
                }
            }
        }
        GBAR();

        // ---------- Sinkhorn: 20 iterations + final v pass ----------
        const int n4u = RP >> 2;
        const int n4b = CP >> 2;
        for (int it = 0; it <= ITS; it++) {
            // pass1: bv = b / (K^T u)   [rows of KT, u cached in smem]
            for (int idx = tid; idx < n4u; idx += NT)
                *(float4*)&sh[idx * 4] = __ldcg((const float4*)g_u + idx);
            __syncthreads();
            for (int c = gwarp; c < C; c += nwarp) {
                const float4* Kr = (const float4*)(g_KT + (size_t)c * RP);
                float ax = 0, ay = 0, az = 0, aw = 0;
                for (int idx = lane; idx < n4u; idx += 32) {
                    float4 k4 = __ldcg(Kr + idx);
                    float4 u4 = *(const float4*)&sh[idx * 4];
                    ax = fmaf(k4.x, u4.x, ax); ay = fmaf(k4.y, u4.y, ay);
                    az = fmaf(k4.z, u4.z, az); aw = fmaf(k4.w, u4.w, aw);
                }
                float acc = (ax + ay) + (az + aw);
                acc = warpSumF(acc);
                if (lane == 0) g_bv[c] = ((c < nc) ? b_in : b_last) / acc;
            }
            GBAR();
            if (it == ITS) break;     // bv now holds final v

            // pass2: u = a / (K bv)   [rows of K, bv cached in smem]
            for (int idx = tid; idx < n4b; idx += NT)
                *(float4*)&sh[idx * 4] = __ldcg((const float4*)g_bv + idx);
            __syncthreads();
            for (int r2 = gwarp; r2 < R; r2 += nwarp) {
                const float4* Kr = (const float4*)(g_K + (size_t)r2 * CP);
                float ax = 0, ay = 0, az = 0, aw = 0;
                for (int idx = lane; idx < n4b; idx += 32) {
                    float4 k4 = __ldcg(Kr + idx);
                    float4 b4 = *(const float4*)&sh[idx * 4];
                    ax = fmaf(k4.x, b4.x, ax); ay = fmaf(k4.y, b4.y, ay);
                    az = fmaf(k4.z, b4.z, az); aw = fmaf(k4.w, b4.w, aw);
                }
                float acc = (ax + ay) + (az + aw);
                acc = warpSumF(acc);
                if (lane == 0) g_u[r2] = ((r2 < nt) ? a_in : a_last) / acc;
            }
            GBAR();
        }

        // ---------- Final: 2 * sum_{i,j} u_i K_ij v_j Mt_ij ----------
        {
            for (int idx = tid; idx < n4b; idx += NT)
                *(float4*)&sh[idx * 4] = __ldcg((const float4*)g_bv + idx);
            __syncthreads();
            double wacc = 0.0;
            for (int r2 = gwarp; r2 < R; r2 += nwarp) {
                const float4* Kr = (const float4*)(g_K + (size_t)r2 * CP);
                const float4* Mr = (const float4*)(g_M + (size_t)r2 * CP);
                const bool lastRow = (r2 == nt);
                float acc = 0.0f;
                for (int idx = lane; idx < n4b; idx += 32) {
                    float4 k4 = __ldcg(Kr + idx);
                    float4 v4 = *(const float4*)&sh[idx * 4];
                    float4 m4 = __ldcg(Mr + idx);   // row nt reads zeros (never written) - safe
                    int j = idx * 4;
                    float mt0, mt1, mt2, mt3;
                    if (lastRow) {
                        mt0 = (j+0 < nc) ? delta : 0.0f;
                        mt1 = (j+1 < nc) ? delta : 0.0f;
                        mt2 = (j+2 < nc) ? delta : 0.0f;
                        mt3 = (j+3 < nc) ? delta : 0.0f;
                    } else {
                        mt0 = (j+0 < nc) ? m4.x : ((j+0 == nc) ? delta : 0.0f);
                        mt1 = (j+1 < nc) ? m4.y : ((j+1 == nc) ? delta : 0.0f);
                        mt2 = (j+2 < nc) ? m4.z : ((j+2 == nc) ? delta : 0.0f);
                        mt3 = (j+3 < nc) ? m4.w : ((j+3 == nc) ? delta : 0.0f);
                    }
                    acc = fmaf(k4.x * v4.x, mt0, acc);
                    acc = fmaf(k4.y * v4.y, mt1, acc);
                    acc = fmaf(k4.z * v4.z, mt2, acc);
                    acc = fmaf(k4.w * v4.w, mt3, acc);
                }
                acc = warpSumF(acc);
                if (lane == 0) wacc += (double)(__ldcg(&g_u[r2]) * acc);
            }
            __syncthreads();
            if (lane == 0) s_d[wid] = wacc;
            __syncthreads();
            if (wid == 0) {
                double t2 = s_d[lane];
                t2 = warpSumD(t2);
                if (lane == 0) g_pres[bid] = t2;
            }
        }
        GBAR();
        if (bid == 0 && tid == 0) {
            double ts = 0.0;
            #pragma unroll 8
            for (int k2 = 0; k2 < NB; k2++) ts += __ldcg(&g_pres[k2]);
            total += 2.0 * ts;
        }
    }

    if (bid == 0 && tid == 0) out[0] = (float)total;
}

extern "C" void kernel_launch(void* const* d_in, const int* in_sizes, int n_in,
                              void* d_out, int out_size) {
    const float* X = (const float*)d_in[0];
    const int*   T = (const int*)d_in[1];
    float* out = (float*)d_out;
    (void)in_sizes; (void)n_in; (void)out_size;
    sinkhorn_all<<<NB, NT>>>(X, T, out);
}

// round 3
// speedup vs baseline: 1.7511x; 1.7511x over previous
#include <cuda_runtime.h>
#include <cuda_fp16.h>
#include <math.h>
#include <float.h>

#define NB 128          // total blocks
#define GROUPS 4        // independent groups
#define GNB 32          // blocks per group
#define SPG 8           // timesteps per group (GROUPS*SPG = 32)
#define NT 1024         // threads per block
#define N_ 4096
#define S_ 32
#define D_ 128
#define MAXP 4224       // worst-case padded dim
#define ITS 20
#define EPSK 1e-6f

// ---------------- persistent scratch (__device__ globals: allocation-free) ----------------
__device__ __align__(16) float  g_Xg[(size_t)S_ * N_ * D_];        // permuted features [s][r][d]
__device__ float  g_nrm[S_ * N_];                                  // squared norms [s][r]
__device__ __align__(16) float  g_M [(size_t)GROUPS * MAXP * MAXP]; // per-group cost matrix (fp32)
__device__ __align__(16) __half g_K [(size_t)GROUPS * MAXP * MAXP]; // per-group K   (fp16)
__device__ __align__(16) __half g_KT[(size_t)GROUPS * MAXP * MAXP]; // per-group K^T (fp16)
__device__ __align__(16) float  g_u [GROUPS][MAXP];
__device__ __align__(16) float  g_bv[GROUPS][MAXP];
__device__ int    g_perm[GROUPS][N_];
__device__ int    g_ntA [GROUPS];
__device__ float  g_pA  [GROUPS];
__device__ float  g_pmax[GROUPS][GNB];
__device__ double g_psum[GROUPS][GNB];
__device__ double g_pres[GROUPS][GNB];
__device__ double g_res [S_];
__device__ unsigned long long g_barCnt[GROUPS * 16];   // 128B apart per group
__device__ unsigned long long g_doneCnt;

// ---------------- group barrier: monotonic 64-bit counter ----------------
__device__ __forceinline__ void gbar_sync(unsigned long long* cnt, unsigned long long tgt) {
    __syncthreads();
    if (threadIdx.x == 0) {
        __threadfence();
        atomicAdd(cnt, 1ULL);
        while (*(volatile unsigned long long*)cnt < tgt) { __nanosleep(64); }
        __threadfence();
    }
    __syncthreads();
}
#define GBAR() do { ++barK; gbar_sync(cntp, barBase + (unsigned long long)barK * GNB); } while (0)

// ---------------- FFMA-only expf ----------------
__device__ __forceinline__ float fast_exp(float x) {
    const float L2E = 1.4426950408889634f;
    float y = fmaf(x, L2E, 12582912.0f);
    int   n = __float_as_int(y) - 0x4B400000;
    float r = y - 12582912.0f;
    float f = fmaf(x, L2E, -r);
    float p =        1.540353040e-4f;
    p = fmaf(p, f,   1.333355815e-3f);
    p = fmaf(p, f,   9.618129107e-3f);
    p = fmaf(p, f,   5.550410866e-2f);
    p = fmaf(p, f,   2.402265070e-1f);
    p = fmaf(p, f,   6.931471806e-1f);
    p = fmaf(p, f,   1.0f);
    return p * __int_as_float((n + 127) << 23);
}

__device__ __forceinline__ float warpMaxF(float v) {
    #pragma unroll
    for (int o = 16; o; o >>= 1) v = fmaxf(v, __shfl_down_sync(0xffffffffu, v, o));
    return v;
}
__device__ __forceinline__ float warpSumF(float v) {
    #pragma unroll
    for (int o = 16; o; o >>= 1) v += __shfl_down_sync(0xffffffffu, v, o);
    return v;
}
__device__ __forceinline__ double warpSumD(double v) {
    #pragma unroll
    for (int o = 16; o; o >>= 1) v += __shfl_down_sync(0xffffffffu, v, o);
    return v;
}

// ---------------- packed f32x2 FMA (ptxas never auto-fuses; PTX-only) ----------------
__device__ __forceinline__ unsigned long long pk2f(float a, float b) {
    unsigned long long r;
    asm("mov.b64 %0, {%1, %2};" : "=l"(r) : "f"(a), "f"(b));
    return r;
}
__device__ __forceinline__ float2 upk2f(unsigned long long v) {
    float2 r;
    asm("mov.b64 {%0, %1}, %2;" : "=f"(r.x), "=f"(r.y) : "l"(v));
    return r;
}
__device__ __forceinline__ void fmaf2(unsigned long long& d, unsigned long long a, unsigned long long b) {
    asm("fma.rn.f32x2 %0, %1, %2, %0;" : "+l"(d) : "l"(a), "l"(b));
}

__global__ void __launch_bounds__(NT, 1)
sinkhorn_all(const float* __restrict__ X, const int* __restrict__ T, float* __restrict__ out)
{
    __shared__ __align__(16) float sh[8448];
    __shared__ float  s_f[32];
    __shared__ double s_d[32];
    __shared__ float  s_delta, s_efflam;

    const int tid  = threadIdx.x;
    const int bid  = blockIdx.x;
    const int lane = tid & 31;
    const int wid  = tid >> 5;
    const int grp  = bid >> 5;          // bid / GNB
    const int lb   = bid & 31;          // block within group
    const int gw   = lb * 32 + wid;     // warp within group (0..1023)
    const int GW   = GNB * 32;

    unsigned long long* cntp = &g_barCnt[grp * 16];
    unsigned long long v0 = *(volatile unsigned long long*)cntp;
    unsigned long long barBase = v0 - (v0 % (unsigned long long)GNB);
    int barK = 0;

    // done-counter base read up-front (before any arrivals this launch)
    unsigned long long doneBase = 0;
    if (bid == 0 && tid == 0) {
        unsigned long long dv = *(volatile unsigned long long*)&g_doneCnt;
        doneBase = dv - (dv % (unsigned long long)NB);
    }

    float*  Mg  = g_M  + (size_t)grp * MAXP * MAXP;
    __half* Kg  = g_K  + (size_t)grp * MAXP * MAXP;
    __half* KTg = g_KT + (size_t)grp * MAXP * MAXP;
    float*  ug  = g_u [grp];
    float*  bvg = g_bv[grp];
    int*    permg = g_perm[grp];

    // ---------------- A0: each group's block 0 builds the stable permutation ----------------
    if (lb == 0) {
        int* cnt = (int*)sh;
        int base = tid * 4;
        int tv0 = T[base], tv1 = T[base+1], tv2 = T[base+2], tv3 = T[base+3];
        int c = (tv0 > 0) + (tv1 > 0) + (tv2 > 0) + (tv3 > 0);
        cnt[tid] = c;
        __syncthreads();
        for (int off = 1; off < NT; off <<= 1) {
            int vv  = cnt[tid];
            int add = (tid >= off) ? cnt[tid - off] : 0;
            __syncthreads();
            cnt[tid] = vv + add;
            __syncthreads();
        }
        int total = cnt[NT - 1];
        int excl  = cnt[tid] - c;
        int tpos = excl, cpos = total + base - excl;
        if (tv0 > 0) permg[tpos++] = base + 0; else permg[cpos++] = base + 0;
        if (tv1 > 0) permg[tpos++] = base + 1; else permg[cpos++] = base + 1;
        if (tv2 > 0) permg[tpos++] = base + 2; else permg[cpos++] = base + 2;
        if (tv3 > 0) permg[tpos++] = base + 3; else permg[cpos++] = base + 3;
        if (tid == NT - 1) { g_ntA[grp] = total; g_pA[grp] = (float)total / (float)N_; }
    }
    GBAR();

    const int   nt = g_ntA[grp];
    const int   nc = N_ - nt;
    const float p  = g_pA[grp];
    const int   R = nt + 1, C = nc + 1;
    const int   RP = (R + 127) & ~127;
    const int   CP = (C + 127) & ~127;
    const float a_in = p / (float)nt, a_last = 1.0f - p;
    const float b_in = (1.0f - p) / (float)nc, b_last = p;

    // ---------------- A1: gather this group's 8 timesteps + squared norms ----------------
    for (int job = gw; job < SPG * N_; job += GW) {
        int s = grp * SPG + (job >> 12);
        int r = job & (N_ - 1);
        int src = permg[r];
        const float4* sp = (const float4*)(X + ((size_t)src * S_ + s) * D_);
        float4 vv = sp[lane];
        ((float4*)(g_Xg + ((size_t)s * N_ + r) * D_))[lane] = vv;
        float sq = vv.x*vv.x + vv.y*vv.y + vv.z*vv.z + vv.w*vv.w;
        sq = warpSumF(sq);
        if (lane == 0) g_nrm[s * N_ + r] = sq;
    }
    GBAR();

    // ================== per-timestep loop (8 steps, group-local) ==================
    for (int sl = 0; sl < SPG; sl++) {
        const int s = grp * SPG + sl;
        const float* Xt  = g_Xg + (size_t)s * N_ * D_;
        const float* nrm = g_nrm + s * N_;

        // ---------- B1: M = nx + ny - 2*Xt*Xc^T (128x128 tiles, 4x4/thread, f32x2 FMA) ----------
        {
            float* As = sh;
            float* Bs = sh + 4096;
            const int tilesI = (nt + 127) >> 7;
            const int tilesJ = (nc + 127) >> 7;
            const int nTiles = tilesI * tilesJ;
            const int lrow = tid & 127;
            const int ld4  = tid >> 7;
            const int tx = lane;
            const int ty = wid;
            float  lmax = -FLT_MAX;
            double lsum = 0.0;

            for (int tile = lb; tile < nTiles; tile += GNB) {
                int ti = tile / tilesJ, tj = tile - ti * tilesJ;
                int i0 = ti << 7, j0 = tj << 7;
                int arow = i0 + lrow; if (arow >= nt) arow = nt - 1;
                int brow = j0 + lrow; if (brow >= nc) brow = nc - 1;
                const float* ap = Xt + (size_t)arow * D_ + ld4 * 4;
                const float* bp = Xt + (size_t)(nt + brow) * D_ + ld4 * 4;

                unsigned long long acc2[4][2] = {};

                for (int d0 = 0; d0 < D_; d0 += 32) {
                    __syncthreads();
                    float4 av = *(const float4*)(ap + d0);
                    float4 bw = *(const float4*)(bp + d0);
                    int dd0 = ld4 * 4;
                    As[(dd0+0)*128 + lrow] = av.x;  As[(dd0+1)*128 + lrow] = av.y;
                    As[(dd0+2)*128 + lrow] = av.z;  As[(dd0+3)*128 + lrow] = av.w;
                    Bs[(dd0+0)*128 + lrow] = bw.x;  Bs[(dd0+1)*128 + lrow] = bw.y;
                    Bs[(dd0+2)*128 + lrow] = bw.z;  Bs[(dd0+3)*128 + lrow] = bw.w;
                    __syncthreads();
                    #pragma unroll
                    for (int dd = 0; dd < 32; dd++) {
                        float4 a4 = *(const float4*)&As[dd*128 + ty*4];
                        ulonglong2 b2 = *(const ulonglong2*)&Bs[dd*128 + tx*4];
                        unsigned long long ax = pk2f(a4.x, a4.x);
                        unsigned long long ay = pk2f(a4.y, a4.y);
                        unsigned long long az = pk2f(a4.z, a4.z);
                        unsigned long long aw = pk2f(a4.w, a4.w);
                        fmaf2(acc2[0][0], ax, b2.x); fmaf2(acc2[0][1], ax, b2.y);
                        fmaf2(acc2[1][0], ay, b2.x); fmaf2(acc2[1][1], ay, b2.y);
                        fmaf2(acc2[2][0], az, b2.x); fmaf2(acc2[2][1], az, b2.y);
                        fmaf2(acc2[3][0], aw, b2.x); fmaf2(acc2[3][1], aw, b2.y);
                    }
                }
                float tsum = 0.0f;
                #pragma unroll
                for (int rr = 0; rr < 4; rr++) {
                    int i = i0 + ty * 4 + rr;
                    if (i >= nt) break;
                    float nx = nrm[i];
                    float2 c01 = upk2f(acc2[rr][0]);
                    float2 c23 = upk2f(acc2[rr][1]);
                    float cv[4] = { c01.x, c01.y, c23.x, c23.y };
                    #pragma unroll
                    for (int cc = 0; cc < 4; cc++) {
                        int j = j0 + tx * 4 + cc;
                        if (j >= nc) break;
                        float m = fmaf(-2.0f, cv[cc], nx + nrm[nt + j]);
                        Mg[(size_t)i * CP + j] = m;
                        lmax = fmaxf(lmax, m);
                        tsum += m;
                    }
                }
                lsum += (double)tsum;
            }
            lmax = warpMaxF(lmax);
            lsum = warpSumD(lsum);
            __syncthreads();
            if (lane == 0) { s_f[wid] = lmax; s_d[wid] = lsum; }
            __syncthreads();
            if (wid == 0) {
                float  m2 = s_f[lane];
                double s2 = s_d[lane];
                m2 = warpMaxF(m2);
                s2 = warpSumD(s2);
                if (lane == 0) { g_pmax[grp][lb] = m2; g_psum[grp][lb] = s2; }
            }
        }
        GBAR();

        // ---------- B2: every block reduces the GNB partials (identical fixed tree) ----------
        if (wid == 0) {
            float  dmax = __ldcg(&g_pmax[grp][lane]);
            double dsum = __ldcg(&g_psum[grp][lane]);
            dmax = warpMaxF(dmax);
            dsum = warpSumD(dsum);
            if (lane == 0) {
                s_delta  = dmax;
                s_efflam = (float)(((double)nt * (double)nc) / dsum);
            }
        }
        __syncthreads();
        const float delta  = s_delta;
        const float efflam = s_efflam;

        // ---------- B3: K = exp(-efflam*Mt)+eps (fp16), K^T via smem transpose ----------
        {
            const int rowStrips = RP >> 5, colStrips = CP >> 7;
            const int nStr = rowStrips * colStrips;
            const int srow = wid;
            const int tj = tid >> 3;
            const int io = (tid & 7) * 4;
            const float kdelta = fast_exp(-efflam * delta) + EPSK;

            for (int str = lb; str < nStr; str += GNB) {
                int sr = str / colStrips, sc = str - sr * colStrips;
                int i0 = sr << 5, j0 = sc << 7;
                int i = i0 + srow;
                float kq[4];
                #pragma unroll
                for (int q = 0; q < 4; q++) {
                    int j = j0 + lane * 4 + q;
                    float kv;
                    if (i < nt && j < nc) {
                        float m = __ldcg(&Mg[(size_t)i * CP + j]);
                        kv = fast_exp(-efflam * m) + EPSK;
                    } else if (i == nt && j < nc) kv = kdelta;
                    else if (j == nc && i < nt)   kv = kdelta;
                    else if (i == nt && j == nc)  kv = 1.0f + EPSK;
                    else                          kv = 0.0f;
                    kq[q] = kv;
                    sh[srow * 133 + lane * 4 + q] = kv;
                }
                {
                    union { __half2 h[2]; uint2 u; } cv;
                    cv.h[0] = __floats2half2_rn(kq[0], kq[1]);
                    cv.h[1] = __floats2half2_rn(kq[2], kq[3]);
                    *(uint2*)&Kg[(size_t)i * CP + j0 + lane * 4] = cv.u;
                }
                __syncthreads();
                {
                    union { __half2 h[2]; uint2 u; } cv;
                    cv.h[0] = __floats2half2_rn(sh[(io+0)*133 + tj], sh[(io+1)*133 + tj]);
                    cv.h[1] = __floats2half2_rn(sh[(io+2)*133 + tj], sh[(io+3)*133 + tj]);
                    *(uint2*)&KTg[(size_t)(j0 + tj) * RP + i0 + io] = cv.u;
                }
                __syncthreads();
            }
            if (lb == 0) {
                for (int r2 = tid; r2 < RP; r2 += NT) {
                    ug[r2] = (r2 < nt) ? a_in : ((r2 == nt) ? a_last : 0.0f);
                }
            }
        }
        GBAR();

        // ---------- Sinkhorn: 20 iterations + final v pass (fp16 K, fp32 math) ----------
        const int chU = RP >> 3;   // 8-half chunks per KT row
        const int chB = CP >> 3;   // 8-half chunks per K row
        for (int it = 0; it <= ITS; it++) {
            // pass1: bv = b / (K^T u)
            for (int idx = tid; idx < RP; idx += NT) sh[idx] = __ldcg(&ug[idx]);
            __syncthreads();
            for (int c = gw; c < C; c += GW) {
                const uint4* Kr = (const uint4*)(KTg + (size_t)c * RP);
                float a0 = 0.0f, a1 = 0.0f;
                for (int idx = lane; idx < chU; idx += 32) {
                    uint4 kv = __ldcg(Kr + idx);
                    const __half2* hp = (const __half2*)&kv;
                    float4 u0 = *(const float4*)&sh[idx * 8];
                    float4 u1 = *(const float4*)&sh[idx * 8 + 4];
                    float2 f0 = __half22float2(hp[0]);
                    float2 f1 = __half22float2(hp[1]);
                    float2 f2 = __half22float2(hp[2]);
                    float2 f3 = __half22float2(hp[3]);
                    a0 = fmaf(f0.x, u0.x, a0); a1 = fmaf(f0.y, u0.y, a1);
                    a0 = fmaf(f1.x, u0.z, a0); a1 = fmaf(f1.y, u0.w, a1);
                    a0 = fmaf(f2.x, u1.x, a0); a1 = fmaf(f2.y, u1.y, a1);
                    a0 = fmaf(f3.x, u1.z, a0); a1 = fmaf(f3.y, u1.w, a1);
                }
                float acc = warpSumF(a0 + a1);
                if (lane == 0) bvg[c] = ((c < nc) ? b_in : b_last) / acc;
            }
            GBAR();
            if (it == ITS) break;   // bv now holds final v

            // pass2: u = a / (K bv)
            for (int idx = tid; idx < CP; idx += NT) sh[idx] = __ldcg(&bvg[idx]);
            __syncthreads();
            for (int r2 = gw; r2 < R; r2 += GW) {
                const uint4* Kr = (const uint4*)(Kg + (size_t)r2 * CP);
                float a0 = 0.0f, a1 = 0.0f;
                for (int idx = lane; idx < chB; idx += 32) {
                    uint4 kv = __ldcg(Kr + idx);
                    const __half2* hp = (const __half2*)&kv;
                    float4 u0 = *(const float4*)&sh[idx * 8];
                    float4 u1 = *(const float4*)&sh[idx * 8 + 4];
                    float2 f0 = __half22float2(hp[0]);
                    float2 f1 = __half22float2(hp[1]);
                    float2 f2 = __half22float2(hp[2]);
                    float2 f3 = __half22float2(hp[3]);
                    a0 = fmaf(f0.x, u0.x, a0); a1 = fmaf(f0.y, u0.y, a1);
                    a0 = fmaf(f1.x, u0.z, a0); a1 = fmaf(f1.y, u0.w, a1);
                    a0 = fmaf(f2.x, u1.x, a0); a1 = fmaf(f2.y, u1.y, a1);
                    a0 = fmaf(f3.x, u1.z, a0); a1 = fmaf(f3.y, u1.w, a1);
                }
                float acc = warpSumF(a0 + a1);
                if (lane == 0) ug[r2] = ((r2 < nt) ? a_in : a_last) / acc;
            }
            GBAR();
        }

        // ---------- Final: 2 * sum_{i,j} u_i K_ij v_j Mt_ij ----------
        {
            for (int idx = tid; idx < CP; idx += NT) sh[idx] = __ldcg(&bvg[idx]);
            __syncthreads();
            double wacc = 0.0;
            for (int r2 = gw; r2 < R; r2 += GW) {
                const uint4*  Kr = (const uint4*)(Kg + (size_t)r2 * CP);
                const float4* Mr = (const float4*)(Mg + (size_t)r2 * CP);
                const bool lastRow = (r2 == nt);
                float acc = 0.0f;
                for (int idx = lane; idx < chB; idx += 32) {
                    uint4 kv = __ldcg(Kr + idx);
                    const __half2* hp = (const __half2*)&kv;
                    float4 m0 = __ldcg(Mr + idx * 2);
                    float4 m1 = __ldcg(Mr + idx * 2 + 1);
                    float4 v0 = *(const float4*)&sh[idx * 8];
                    float4 v1 = *(const float4*)&sh[idx * 8 + 4];
                    float2 f0 = __half22float2(hp[0]);
                    float2 f1 = __half22float2(hp[1]);
                    float2 f2 = __half22float2(hp[2]);
                    float2 f3 = __half22float2(hp[3]);
                    int j = idx * 8;
                    float mt[8];
                    if (lastRow) {
                        #pragma unroll
                        for (int q = 0; q < 8; q++) mt[q] = (j + q < nc) ? delta : 0.0f;
                    } else {
                        float mm[8] = { m0.x, m0.y, m0.z, m0.w, m1.x, m1.y, m1.z, m1.w };
                        #pragma unroll
                        for (int q = 0; q < 8; q++)
                            mt[q] = (j + q < nc) ? mm[q] : ((j + q == nc) ? delta : 0.0f);
                    }
                    acc = fmaf(f0.x * v0.x, mt[0], acc);
                    acc = fmaf(f0.y * v0.y, mt[1], acc);
                    acc = fmaf(f1.x * v0.z, mt[2], acc);
                    acc = fmaf(f1.y * v0.w, mt[3], acc);
                    acc = fmaf(f2.x * v1.x, mt[4], acc);
                    acc = fmaf(f2.y * v1.y, mt[5], acc);
                    acc = fmaf(f3.x * v1.z, mt[6], acc);
                    acc = fmaf(f3.y * v1.w, mt[7], acc);
                }
                acc = warpSumF(acc);
                if (lane == 0) wacc += (double)(__ldcg(&ug[r2]) * acc);
            }
            __syncthreads();
            if (lane == 0) s_d[wid] = wacc;
            __syncthreads();
            if (wid == 0) {
                double t2 = warpSumD(s_d[lane]);
                if (lane == 0) g_pres[grp][lb] = t2;
            }
        }
        GBAR();
        if (lb == 0 && tid == 0) {
            double ts = 0.0;
            #pragma unroll 8
            for (int k2 = 0; k2 < GNB; k2++) ts += __ldcg(&g_pres[grp][k2]);
            g_res[s] = 2.0 * ts;
        }
    }

    // ---------------- global combine: done-counter, then fixed-order sum ----------------
    __threadfence();
    __syncthreads();
    if (tid == 0) atomicAdd(&g_doneCnt, 1ULL);
    if (bid == 0 && tid == 0) {
        unsigned long long tgt = doneBase + (unsigned long long)NB;
        while (*(volatile unsigned long long*)&g_doneCnt < tgt) { __nanosleep(128); }
        __threadfence();
        double total = 0.0;
        for (int s = 0; s < S_; s++) total += __ldcg(&g_res[s]);
        out[0] = (float)total;
    }
}

extern "C" void kernel_launch(void* const* d_in, const int* in_sizes, int n_in,
                              void* d_out, int out_size) {
    const float* X = (const float*)d_in[0];
    const int*   T = (const int*)d_in[1];
    float* out = (float*)d_out;
    (void)in_sizes; (void)n_in; (void)out_size;
    sinkhorn_all<<<NB, NT>>>(X, T, out);
}